// round 2
// baseline (speedup 1.0000x reference)
#include <cuda_runtime.h>

// Problem constants
#define NN   131072      // total nodes (B*N)
#define DIMF 128         // embedding dim
#define EDG  1048576     // edges
#define INF  74          // input feats

// ---------------- device scratch (allocation-free rule) ----------------
__device__ float g_hA[NN * DIMF];     // 64MB ping
__device__ float g_hB[NN * DIMF];     // 64MB pong
__device__ float g_nsrc[NN];          // rsqrt(max(deg_out,1))
__device__ float g_ndst[NN];          // rsqrt(max(deg_in,1))
__device__ int   g_deg_out[NN];
__device__ int   g_deg_in[NN];
__device__ int   g_cursor[NN];
__device__ int   g_rstart[NN];        // CSR row starts (by dst)
__device__ int   g_csr[EDG];          // src index per CSR slot
__device__ int   g_bsum[128];
__device__ int   g_boff[128];

// ---------------- helpers ----------------
__global__ void k_zero() {
    int i = blockIdx.x * blockDim.x + threadIdx.x;
    if (i < NN) { g_deg_out[i] = 0; g_deg_in[i] = 0; g_cursor[i] = 0; }
}

__global__ void k_count(const int* __restrict__ src, const int* __restrict__ dst) {
    int stride = gridDim.x * blockDim.x;
    for (int e = blockIdx.x * blockDim.x + threadIdx.x; e < EDG; e += stride) {
        atomicAdd(&g_deg_out[src[e]], 1);
        atomicAdd(&g_deg_in[dst[e]], 1);
    }
}

// Block-local exclusive scan of deg_in (1024 elems/block, 128 blocks)
__global__ void k_scanA() {
    __shared__ int sh[1024];
    int i = blockIdx.x * 1024 + threadIdx.x;
    int v = g_deg_in[i];
    sh[threadIdx.x] = v;
    __syncthreads();
#pragma unroll
    for (int off = 1; off < 1024; off <<= 1) {
        int t = (threadIdx.x >= off) ? sh[threadIdx.x - off] : 0;
        __syncthreads();
        sh[threadIdx.x] += t;
        __syncthreads();
    }
    g_rstart[i] = sh[threadIdx.x] - v;       // exclusive within block
    if (threadIdx.x == 1023) g_bsum[blockIdx.x] = sh[1023];
}

__global__ void k_scanB() {
    __shared__ int sh[128];
    int v = g_bsum[threadIdx.x];
    sh[threadIdx.x] = v;
    __syncthreads();
#pragma unroll
    for (int off = 1; off < 128; off <<= 1) {
        int t = (threadIdx.x >= off) ? sh[threadIdx.x - off] : 0;
        __syncthreads();
        sh[threadIdx.x] += t;
        __syncthreads();
    }
    g_boff[threadIdx.x] = sh[threadIdx.x] - v;  // exclusive
}

__global__ void k_scanC_norm() {
    int i = blockIdx.x * blockDim.x + threadIdx.x;
    if (i < NN) {
        g_rstart[i] += g_boff[i >> 10];
        g_nsrc[i] = rsqrtf((float)max(g_deg_out[i], 1));
        g_ndst[i] = rsqrtf((float)max(g_deg_in[i], 1));
    }
}

__global__ void k_fill(const int* __restrict__ src, const int* __restrict__ dst) {
    int stride = gridDim.x * blockDim.x;
    for (int e = blockIdx.x * blockDim.x + threadIdx.x; e < EDG; e += stride) {
        int d = dst[e];
        int pos = atomicAdd(&g_cursor[d], 1);
        g_csr[g_rstart[d] + pos] = src[e];
    }
}

// ---------------- init GEMM: hA = (x @ W_init) * nrm_src ----------------
// BM=64, N=128, K=74. Thread tile 8x8, 128 threads.
#define APAD_I 75

__global__ void __launch_bounds__(128)
k_gemm_init(const float* __restrict__ x, const float* __restrict__ Wi) {
    extern __shared__ float sm[];
    float* As = sm;                      // [64][75]  (scalar access only)
    float* Ws = sm + 64 * APAD_I;        // [74][128] (offset 19200 B, 16B-aligned)
    int tid = threadIdx.x;
    int rowBase = blockIdx.x * 64;

    // stage W_init (74*128 = 2368 float4)
    {
        const float4* W4 = (const float4*)Wi;
        float4* Ws4 = (float4*)Ws;
        for (int idx = tid; idx < 2368; idx += 128) Ws4[idx] = W4[idx];
    }
    // stage A tile: 64 rows x 74 cols
    for (int idx = tid; idx < 64 * 74; idx += 128) {
        int r = idx / 74;
        int k = idx - r * 74;
        As[r * APAD_I + k] = x[(rowBase + r) * 74 + k];
    }
    __syncthreads();

    int tr = tid >> 4, tc = tid & 15;
    float acc[8][8];
#pragma unroll
    for (int i = 0; i < 8; i++)
#pragma unroll
        for (int j = 0; j < 8; j++) acc[i][j] = 0.f;

    const float* Ab = &As[tr * 8 * APAD_I];
#pragma unroll 2
    for (int k = 0; k < 74; k++) {
        float a[8];
#pragma unroll
        for (int i = 0; i < 8; i++) a[i] = Ab[i * APAD_I + k];
        float4 b0 = *(const float4*)&Ws[k * 128 + tc * 8];
        float4 b1 = *(const float4*)&Ws[k * 128 + tc * 8 + 4];
        float b[8] = {b0.x, b0.y, b0.z, b0.w, b1.x, b1.y, b1.z, b1.w};
#pragma unroll
        for (int i = 0; i < 8; i++)
#pragma unroll
            for (int j = 0; j < 8; j++) acc[i][j] = fmaf(a[i], b[j], acc[i][j]);
    }

#pragma unroll
    for (int i = 0; i < 8; i++) {
        int r = rowBase + tr * 8 + i;
        float ns = g_nsrc[r];
        float4 o0 = make_float4(acc[i][0] * ns, acc[i][1] * ns, acc[i][2] * ns, acc[i][3] * ns);
        float4 o1 = make_float4(acc[i][4] * ns, acc[i][5] * ns, acc[i][6] * ns, acc[i][7] * ns);
        float4* d4 = (float4*)&g_hA[r * 128 + tc * 8];
        d4[0] = o0; d4[1] = o1;
    }
}

// ---------------- fused layer: gather(CSR) -> (agg*nrm_dst) @ W + b -> relu [-> *nrm_src]
// BM=64 rows per block, full N=128; 128 threads (4 warps). MODE 1: write hn (scaled);
// MODE 2: write final output (unscaled).
// APAD = 128: 16B-aligned float4 rows (129 caused STG/STS.128 misalignment trap).
// Conflict analysis: Phase-1 stores are lane-consecutive float4 (conflict-free);
// GEMM A-reads hit only 2 distinct addresses per warp (broadcast). No padding needed.
#define APAD 128

template <int MODE>
__global__ void __launch_bounds__(128, 2)
k_layer(const float* __restrict__ hn,
        const float* __restrict__ W,
        const float* __restrict__ bias,
        float* __restrict__ out) {
    extern __shared__ float sm[];
    float* As = sm;                 // [64][128]
    float* Ws = sm + 64 * APAD;     // [128][128]
    int tid = threadIdx.x;
    int lane = tid & 31, warp = tid >> 5;
    int rowBase = blockIdx.x * 64;

    // stage weights (16384 floats = 4096 float4)
    {
        const float4* W4 = (const float4*)W;
        float4* Ws4 = (float4*)Ws;
#pragma unroll
        for (int idx = 0; idx < 32; ++idx) Ws4[tid + idx * 128] = W4[tid + idx * 128];
    }

    // ---- Phase 1: gather + nrm_dst scale into shared A tile ----
    const float4* h4 = (const float4*)hn;
    for (int rr = 0; rr < 16; ++rr) {
        int r = warp * 16 + rr;
        int n = rowBase + r;
        int j0 = g_rstart[n];
        int cnt = g_deg_in[n];
        float4 acc = make_float4(0.f, 0.f, 0.f, 0.f);
        int j = 0;
        for (; j + 4 <= cnt; j += 4) {
            int s0 = g_csr[j0 + j];
            int s1 = g_csr[j0 + j + 1];
            int s2 = g_csr[j0 + j + 2];
            int s3 = g_csr[j0 + j + 3];
            float4 v0 = h4[s0 * 32 + lane];
            float4 v1 = h4[s1 * 32 + lane];
            float4 v2 = h4[s2 * 32 + lane];
            float4 v3 = h4[s3 * 32 + lane];
            acc.x += (v0.x + v1.x) + (v2.x + v3.x);
            acc.y += (v0.y + v1.y) + (v2.y + v3.y);
            acc.z += (v0.z + v1.z) + (v2.z + v3.z);
            acc.w += (v0.w + v1.w) + (v2.w + v3.w);
        }
        for (; j < cnt; ++j) {
            int s = g_csr[j0 + j];
            float4 v = h4[s * 32 + lane];
            acc.x += v.x; acc.y += v.y; acc.z += v.z; acc.w += v.w;
        }
        float nd = g_ndst[n];
        float4 st = make_float4(acc.x * nd, acc.y * nd, acc.z * nd, acc.w * nd);
        *(float4*)&As[r * APAD + lane * 4] = st;
    }
    __syncthreads();

    // ---- Phase 2: 64x128 GEMM (K=128), thread tile 8x8 ----
    int tr = tid >> 4, tc = tid & 15;
    float acc[8][8];
#pragma unroll
    for (int i = 0; i < 8; i++)
#pragma unroll
        for (int j = 0; j < 8; j++) acc[i][j] = 0.f;

    const float* Ab = &As[tr * 8 * APAD];
#pragma unroll 4
    for (int k = 0; k < 128; k++) {
        float a[8];
#pragma unroll
        for (int i = 0; i < 8; i++) a[i] = Ab[i * APAD + k];
        float4 b0 = *(const float4*)&Ws[k * 128 + tc * 8];
        float4 b1 = *(const float4*)&Ws[k * 128 + tc * 8 + 4];
        float b[8] = {b0.x, b0.y, b0.z, b0.w, b1.x, b1.y, b1.z, b1.w};
#pragma unroll
        for (int i = 0; i < 8; i++)
#pragma unroll
            for (int j = 0; j < 8; j++) acc[i][j] = fmaf(a[i], b[j], acc[i][j]);
    }

    // ---- Epilogue: +bias, relu, optional *nrm_src ----
    float4 bb0 = *(const float4*)&bias[tc * 8];
    float4 bb1 = *(const float4*)&bias[tc * 8 + 4];
    float b[8] = {bb0.x, bb0.y, bb0.z, bb0.w, bb1.x, bb1.y, bb1.z, bb1.w};
#pragma unroll
    for (int i = 0; i < 8; i++) {
        int r = rowBase + tr * 8 + i;
        float ns = (MODE == 1) ? g_nsrc[r] : 1.f;
        float v[8];
#pragma unroll
        for (int j = 0; j < 8; j++) {
            float t = acc[i][j] + b[j];
            t = fmaxf(t, 0.f);
            v[j] = t * ns;
        }
        float4* d4 = (float4*)&out[r * 128 + tc * 8];
        d4[0] = make_float4(v[0], v[1], v[2], v[3]);
        d4[1] = make_float4(v[4], v[5], v[6], v[7]);
    }
}

// ---------------- launch ----------------
extern "C" void kernel_launch(void* const* d_in, const int* in_sizes, int n_in,
                              void* d_out, int out_size) {
    (void)in_sizes; (void)n_in; (void)out_size;
    const float* x   = (const float*)d_in[0];
    const int*   src = (const int*)d_in[1];
    const int*   dst = (const int*)d_in[2];
    const float* Wi  = (const float*)d_in[3];
    const float* W1  = (const float*)d_in[4];
    const float* b1  = (const float*)d_in[5];
    const float* W2  = (const float*)d_in[6];
    const float* b2  = (const float*)d_in[7];
    const float* W3  = (const float*)d_in[8];
    const float* b3  = (const float*)d_in[9];
    float* out = (float*)d_out;

    const int SMEM_INIT  = (64 * APAD_I + 74 * 128) * 4;   // 57,088 B
    const int SMEM_LAYER = (64 * APAD + 128 * 128) * 4;    // 98,304 B

    cudaFuncSetAttribute(k_gemm_init, cudaFuncAttributeMaxDynamicSharedMemorySize, SMEM_INIT);
    cudaFuncSetAttribute(k_layer<1>, cudaFuncAttributeMaxDynamicSharedMemorySize, SMEM_LAYER);
    cudaFuncSetAttribute(k_layer<2>, cudaFuncAttributeMaxDynamicSharedMemorySize, SMEM_LAYER);

    float *hA, *hB;
    cudaGetSymbolAddress((void**)&hA, g_hA);
    cudaGetSymbolAddress((void**)&hB, g_hB);

    // graph preprocessing (per call; all kernel launches — graph-capturable)
    k_zero<<<(NN + 255) / 256, 256>>>();
    k_count<<<1024, 256>>>(src, dst);
    k_scanA<<<NN / 1024, 1024>>>();
    k_scanB<<<1, 128>>>();
    k_scanC_norm<<<(NN + 255) / 256, 256>>>();
    k_fill<<<1024, 256>>>(src, dst);

    // hA = (x @ W_init) * nrm_src
    k_gemm_init<<<NN / 64, 128, SMEM_INIT>>>(x, Wi);

    // 3 GCN layers (ping-pong; layer 3 writes d_out unscaled)
    k_layer<1><<<NN / 64, 128, SMEM_LAYER>>>(hA, W1, b1, hB);
    k_layer<1><<<NN / 64, 128, SMEM_LAYER>>>(hB, W2, b2, hA);
    k_layer<2><<<NN / 64, 128, SMEM_LAYER>>>(hA, W3, b3, out);
}

// round 4
// speedup vs baseline: 1.5599x; 1.5599x over previous
#include <cuda_runtime.h>
#include <cstdint>

// Problem constants
#define NN   131072      // total nodes (B*N)
#define DIMF 128         // embedding dim
#define EDG  1048576     // edges
#define INF  74          // input feats

// ---------------- device scratch (allocation-free rule) ----------------
__device__ float g_hA[NN * DIMF];     // 64MB ping
__device__ float g_hB[NN * DIMF];     // 64MB pong
__device__ float g_nsrc[NN];          // rsqrt(max(deg_out,1))
__device__ float g_ndst[NN];          // rsqrt(max(deg_in,1))
__device__ int   g_deg_out[NN];
__device__ int   g_deg_in[NN];
__device__ int   g_cursor[NN];
__device__ int   g_rstart[NN];        // CSR row starts (by dst)
__device__ int   g_csr[EDG];          // src index per CSR slot
__device__ int   g_bsum[128];
__device__ int   g_boff[128];

// ---------------- tf32 helpers ----------------
__device__ __forceinline__ float to_tf32(float x) {
    uint32_t u;
    asm("cvt.rna.tf32.f32 %0, %1;" : "=r"(u) : "f"(x));
    return __uint_as_float(u);
}

// D += A*B, m16n8k8 tf32 (A row-major [16][8], B col-major i.e. frag from Bs[n][k])
__device__ __forceinline__ void mma_tf32(float d[4],
                                         uint32_t a0, uint32_t a1, uint32_t a2, uint32_t a3,
                                         uint32_t b0, uint32_t b1) {
    asm volatile(
        "mma.sync.aligned.m16n8k8.row.col.f32.tf32.tf32.f32 "
        "{%0,%1,%2,%3}, {%4,%5,%6,%7}, {%8,%9}, {%0,%1,%2,%3};"
        : "+f"(d[0]), "+f"(d[1]), "+f"(d[2]), "+f"(d[3])
        : "r"(a0), "r"(a1), "r"(a2), "r"(a3), "r"(b0), "r"(b1));
}

// ---------------- preprocessing ----------------
__global__ void k_zero() {
    int i = blockIdx.x * blockDim.x + threadIdx.x;
    if (i < NN) { g_deg_out[i] = 0; g_deg_in[i] = 0; g_cursor[i] = 0; }
}

__global__ void k_count(const int* __restrict__ src, const int* __restrict__ dst) {
    int stride = gridDim.x * blockDim.x;
    for (int e = blockIdx.x * blockDim.x + threadIdx.x; e < EDG; e += stride) {
        atomicAdd(&g_deg_out[src[e]], 1);
        atomicAdd(&g_deg_in[dst[e]], 1);
    }
}

__global__ void k_scanA() {
    __shared__ int sh[1024];
    int i = blockIdx.x * 1024 + threadIdx.x;
    int v = g_deg_in[i];
    sh[threadIdx.x] = v;
    __syncthreads();
#pragma unroll
    for (int off = 1; off < 1024; off <<= 1) {
        int t = (threadIdx.x >= off) ? sh[threadIdx.x - off] : 0;
        __syncthreads();
        sh[threadIdx.x] += t;
        __syncthreads();
    }
    g_rstart[i] = sh[threadIdx.x] - v;
    if (threadIdx.x == 1023) g_bsum[blockIdx.x] = sh[1023];
}

__global__ void k_scanB() {
    __shared__ int sh[128];
    int v = g_bsum[threadIdx.x];
    sh[threadIdx.x] = v;
    __syncthreads();
#pragma unroll
    for (int off = 1; off < 128; off <<= 1) {
        int t = (threadIdx.x >= off) ? sh[threadIdx.x - off] : 0;
        __syncthreads();
        sh[threadIdx.x] += t;
        __syncthreads();
    }
    g_boff[threadIdx.x] = sh[threadIdx.x] - v;
}

__global__ void k_scanC_norm() {
    int i = blockIdx.x * blockDim.x + threadIdx.x;
    if (i < NN) {
        g_rstart[i] += g_boff[i >> 10];
        g_nsrc[i] = rsqrtf((float)max(g_deg_out[i], 1));
        g_ndst[i] = rsqrtf((float)max(g_deg_in[i], 1));
    }
}

__global__ void k_fill(const int* __restrict__ src, const int* __restrict__ dst) {
    int stride = gridDim.x * blockDim.x;
    for (int e = blockIdx.x * blockDim.x + threadIdx.x; e < EDG; e += stride) {
        int d = dst[e];
        int pos = atomicAdd(&g_cursor[d], 1);
        g_csr[g_rstart[d] + pos] = src[e];
    }
}

// ---------------- shared tile strides (floats) ----------------
#define LDA 132          // layer: 128 k + 4 pad (16B-aligned rows, conflict-free frags)
#define LDI 84           // init:  80 k + 4 pad
#define KP_I 80          // K=74 padded to 80 (10 k-steps)

// ================= fused layer kernel =================
// 128 rows/block, 512 threads (16 warps).
// Phase 1: CSR gather + ndst scale -> As (tf32-rounded).  Stage Ws^T -> Bs.
// Phase 2: warp-tiled m16n8k8 tf32 mma, 32x32 per warp (4x4 warp grid).
// Epilogue: +bias, relu, optional *nsrc, st.v2 from fragments.
// MODE 1: out scaled by nsrc (feeds next gather). MODE 2: plain output.
template <int MODE>
__global__ void __launch_bounds__(512, 1)
k_layer_mma(const float* __restrict__ hn,
            const float* __restrict__ W,
            const float* __restrict__ bias,
            float* __restrict__ out) {
    extern __shared__ float sm[];
    float* As = sm;                    // [128][LDA]
    float* Bs = sm + 128 * LDA;        // [128][LDA]  Bs[n][k] = tf32(W[k][n])
    const int tid = threadIdx.x;
    const int lane = tid & 31, warp = tid >> 5;
    const int rowBase = blockIdx.x * 128;

    // ---- stage B = W^T (tf32-rounded) ----
    for (int idx = tid; idx < 128 * 128; idx += 512) {
        int k = idx >> 7, n = idx & 127;
        Bs[n * LDA + k] = to_tf32(W[idx]);
    }

    // ---- gather + ndst scale -> A tile (tf32-rounded), 8 rows per warp ----
    const float4* h4 = (const float4*)hn;
#pragma unroll
    for (int rr = 0; rr < 8; ++rr) {
        int r = warp * 8 + rr;
        int n = rowBase + r;
        int j0 = g_rstart[n];
        int cnt = g_deg_in[n];
        float4 acc = make_float4(0.f, 0.f, 0.f, 0.f);
        int j = 0;
        for (; j + 4 <= cnt; j += 4) {
            int s0 = g_csr[j0 + j];
            int s1 = g_csr[j0 + j + 1];
            int s2 = g_csr[j0 + j + 2];
            int s3 = g_csr[j0 + j + 3];
            float4 v0 = h4[s0 * 32 + lane];
            float4 v1 = h4[s1 * 32 + lane];
            float4 v2 = h4[s2 * 32 + lane];
            float4 v3 = h4[s3 * 32 + lane];
            acc.x += (v0.x + v1.x) + (v2.x + v3.x);
            acc.y += (v0.y + v1.y) + (v2.y + v3.y);
            acc.z += (v0.z + v1.z) + (v2.z + v3.z);
            acc.w += (v0.w + v1.w) + (v2.w + v3.w);
        }
        for (; j < cnt; ++j) {
            int s = g_csr[j0 + j];
            float4 v = h4[s * 32 + lane];
            acc.x += v.x; acc.y += v.y; acc.z += v.z; acc.w += v.w;
        }
        float nd = g_ndst[n];
        float4 st;
        st.x = to_tf32(acc.x * nd);
        st.y = to_tf32(acc.y * nd);
        st.z = to_tf32(acc.z * nd);
        st.w = to_tf32(acc.w * nd);
        *(float4*)&As[r * LDA + lane * 4] = st;
    }
    __syncthreads();

    // ---- Phase 2: warp 32x32 tile. wr,wc in 4x4 grid ----
    const int wr = warp >> 2, wc = warp & 3;
    const int m0 = wr * 32, n0 = wc * 32;
    const int g = lane >> 2, tig = lane & 3;

    float D[2][4][4];   // [m-half][n-sub][frag]
#pragma unroll
    for (int i = 0; i < 2; i++)
#pragma unroll
        for (int j = 0; j < 4; j++)
#pragma unroll
            for (int q = 0; q < 4; q++) D[i][j][q] = 0.f;

    const uint32_t* Au = (const uint32_t*)As;
    const uint32_t* Bu = (const uint32_t*)Bs;

#pragma unroll 4
    for (int k0 = 0; k0 < 128; k0 += 8) {
        uint32_t a[2][4];
#pragma unroll
        for (int i = 0; i < 2; i++) {
            int mr = m0 + i * 16 + g;
            a[i][0] = Au[mr * LDA + k0 + tig];
            a[i][1] = Au[(mr + 8) * LDA + k0 + tig];
            a[i][2] = Au[mr * LDA + k0 + tig + 4];
            a[i][3] = Au[(mr + 8) * LDA + k0 + tig + 4];
        }
        uint32_t b[4][2];
#pragma unroll
        for (int j = 0; j < 4; j++) {
            int nc = n0 + j * 8 + g;
            b[j][0] = Bu[nc * LDA + k0 + tig];
            b[j][1] = Bu[nc * LDA + k0 + tig + 4];
        }
#pragma unroll
        for (int i = 0; i < 2; i++)
#pragma unroll
            for (int j = 0; j < 4; j++)
                mma_tf32(D[i][j], a[i][0], a[i][1], a[i][2], a[i][3], b[j][0], b[j][1]);
    }

    // ---- Epilogue ----
#pragma unroll
    for (int i = 0; i < 2; i++) {
        int r0 = rowBase + m0 + i * 16 + g;     // rows r0 and r0+8
        float ns0 = (MODE == 1) ? g_nsrc[r0] : 1.f;
        float ns1 = (MODE == 1) ? g_nsrc[r0 + 8] : 1.f;
#pragma unroll
        for (int j = 0; j < 4; j++) {
            int col = n0 + j * 8 + tig * 2;
            float bx = bias[col], by = bias[col + 1];
            float2 v0, v1;
            v0.x = fmaxf(D[i][j][0] + bx, 0.f) * ns0;
            v0.y = fmaxf(D[i][j][1] + by, 0.f) * ns0;
            v1.x = fmaxf(D[i][j][2] + bx, 0.f) * ns1;
            v1.y = fmaxf(D[i][j][3] + by, 0.f) * ns1;
            *(float2*)&out[(size_t)r0 * 128 + col] = v0;
            *(float2*)&out[(size_t)(r0 + 8) * 128 + col] = v1;
        }
    }
}

// ================= init kernel: hA = (x @ W_init) * nsrc =================
__global__ void __launch_bounds__(512, 1)
k_init_mma(const float* __restrict__ x, const float* __restrict__ Wi) {
    extern __shared__ float sm[];
    float* As = sm;                    // [128][LDI]
    float* Bs = sm + 128 * LDI;        // [128][LDI]  Bs[n][k] = tf32(Wi[k][n])
    const int tid = threadIdx.x;
    const int lane = tid & 31, warp = tid >> 5;
    const int rowBase = blockIdx.x * 128;

    // A: [128 r][80 k], zero-pad k>=74
    for (int idx = tid; idx < 128 * KP_I; idx += 512) {
        int r = idx / KP_I, k = idx - r * KP_I;
        float v = (k < INF) ? to_tf32(x[(size_t)(rowBase + r) * INF + k]) : 0.f;
        As[r * LDI + k] = v;
    }
    // B: Bs[n][k] = Wi[k][n], zero-pad
    for (int idx = tid; idx < 128 * KP_I; idx += 512) {
        int k = idx >> 7, n = idx & 127;
        float v = (k < INF) ? to_tf32(Wi[k * 128 + n]) : 0.f;
        Bs[n * LDI + k] = v;
    }
    __syncthreads();

    const int wr = warp >> 2, wc = warp & 3;
    const int m0 = wr * 32, n0 = wc * 32;
    const int g = lane >> 2, tig = lane & 3;

    float D[2][4][4];
#pragma unroll
    for (int i = 0; i < 2; i++)
#pragma unroll
        for (int j = 0; j < 4; j++)
#pragma unroll
            for (int q = 0; q < 4; q++) D[i][j][q] = 0.f;

    const uint32_t* Au = (const uint32_t*)As;
    const uint32_t* Bu = (const uint32_t*)Bs;

#pragma unroll
    for (int k0 = 0; k0 < KP_I; k0 += 8) {
        uint32_t a[2][4];
#pragma unroll
        for (int i = 0; i < 2; i++) {
            int mr = m0 + i * 16 + g;
            a[i][0] = Au[mr * LDI + k0 + tig];
            a[i][1] = Au[(mr + 8) * LDI + k0 + tig];
            a[i][2] = Au[mr * LDI + k0 + tig + 4];
            a[i][3] = Au[(mr + 8) * LDI + k0 + tig + 4];
        }
        uint32_t b[4][2];
#pragma unroll
        for (int j = 0; j < 4; j++) {
            int nc = n0 + j * 8 + g;
            b[j][0] = Bu[nc * LDI + k0 + tig];
            b[j][1] = Bu[nc * LDI + k0 + tig + 4];
        }
#pragma unroll
        for (int i = 0; i < 2; i++)
#pragma unroll
            for (int j = 0; j < 4; j++)
                mma_tf32(D[i][j], a[i][0], a[i][1], a[i][2], a[i][3], b[j][0], b[j][1]);
    }

#pragma unroll
    for (int i = 0; i < 2; i++) {
        int r0 = rowBase + m0 + i * 16 + g;
        float ns0 = g_nsrc[r0];
        float ns1 = g_nsrc[r0 + 8];
#pragma unroll
        for (int j = 0; j < 4; j++) {
            int col = n0 + j * 8 + tig * 2;
            float2 v0, v1;
            v0.x = D[i][j][0] * ns0;
            v0.y = D[i][j][1] * ns0;
            v1.x = D[i][j][2] * ns1;
            v1.y = D[i][j][3] * ns1;
            *(float2*)&g_hA[(size_t)r0 * 128 + col] = v0;
            *(float2*)&g_hA[(size_t)(r0 + 8) * 128 + col] = v1;
        }
    }
}

// ---------------- launch ----------------
extern "C" void kernel_launch(void* const* d_in, const int* in_sizes, int n_in,
                              void* d_out, int out_size) {
    (void)in_sizes; (void)n_in; (void)out_size;
    const float* x   = (const float*)d_in[0];
    const int*   src = (const int*)d_in[1];
    const int*   dst = (const int*)d_in[2];
    const float* Wi  = (const float*)d_in[3];
    const float* W1  = (const float*)d_in[4];
    const float* b1  = (const float*)d_in[5];
    const float* W2  = (const float*)d_in[6];
    const float* b2  = (const float*)d_in[7];
    const float* W3  = (const float*)d_in[8];
    const float* b3  = (const float*)d_in[9];
    float* out = (float*)d_out;

    const int SMEM_LAYER = 2 * 128 * LDA * 4;   // 135,168 B
    const int SMEM_INIT  = 2 * 128 * LDI * 4;   // 86,016 B

    cudaFuncSetAttribute(k_init_mma, cudaFuncAttributeMaxDynamicSharedMemorySize, SMEM_INIT);
    cudaFuncSetAttribute(k_layer_mma<1>, cudaFuncAttributeMaxDynamicSharedMemorySize, SMEM_LAYER);
    cudaFuncSetAttribute(k_layer_mma<2>, cudaFuncAttributeMaxDynamicSharedMemorySize, SMEM_LAYER);

    float *hA, *hB;
    cudaGetSymbolAddress((void**)&hA, g_hA);
    cudaGetSymbolAddress((void**)&hB, g_hB);

    // graph preprocessing
    k_zero<<<(NN + 255) / 256, 256>>>();
    k_count<<<1024, 256>>>(src, dst);
    k_scanA<<<NN / 1024, 1024>>>();
    k_scanB<<<1, 128>>>();
    k_scanC_norm<<<(NN + 255) / 256, 256>>>();
    k_fill<<<1024, 256>>>(src, dst);

    // hA = (x @ W_init) * nrm_src  (tf32 tensor cores via mma.sync)
    k_init_mma<<<NN / 128, 512, SMEM_INIT>>>(x, Wi);

    // 3 GCN layers (ping-pong; layer 3 writes d_out unscaled)
    k_layer_mma<1><<<NN / 128, 512, SMEM_LAYER>>>(hA, W1, b1, hB);
    k_layer_mma<1><<<NN / 128, 512, SMEM_LAYER>>>(hB, W2, b2, hA);
    k_layer_mma<2><<<NN / 128, 512, SMEM_LAYER>>>(hA, W3, b3, out);
}